// round 11
// baseline (speedup 1.0000x reference)
#include <cuda_runtime.h>
#include <cuda_bf16.h>
#include <cuda_fp16.h>
#include <cstdint>

#define N_MAX 100000
#define E_MAX 1600000
#define DIM 128

// ---------------------------------------------------------------------------
// Static scratch
__device__ float g_dinv[N_MAX];
__device__ int   g_cnt[N_MAX];
__device__ int   g_rowptr[N_MAX + 1];
__device__ int   g_bsum[128];
__device__ int   g_is64;
__device__ int2  g_stage[E_MAX];         // decoded {row, col}
__device__ int2  g_edge[E_MAX];          // CSR packed {src, norm-as-int}
__device__ __half g_H1h[N_MAX * DIM];    // layer-1 post-GEMM features (fp16)
__device__ __half g_H2h[N_MAX * DIM];    // layer-2 post-GEMM features (fp16)
// bf16 W^T images (hi/lo split), element (n,k) at offset n*128+k
__device__ unsigned short g_W1hi[DIM * DIM], g_W1lo[DIM * DIM];
__device__ unsigned short g_W2hi[DIM * DIM], g_W2lo[DIM * DIM];

// ---------------------------------------------------------------------------
__device__ __forceinline__ int eidx(const void* ei, int is64, int p) {
    return is64 ? (int)((const long long*)ei)[p] : ((const int*)ei)[p];
}

// Zero + dtype probe fused
__global__ void zero_probe_kernel(float* __restrict__ deg, int* __restrict__ cnt,
                                  int N, const long long* __restrict__ ei,
                                  int* __restrict__ flag) {
    int i = blockIdx.x * blockDim.x + threadIdx.x;
    if (i < N) { deg[i] = 0.f; cnt[i] = 0; }
    if (blockIdx.x == 0 && threadIdx.x == 0) {
        int ok = 1;
        for (int j = 0; j < 64; j++) {
            long long v = ei[j];
            if (v < 0 || v >= (long long)N) { ok = 0; break; }
        }
        *flag = ok;
    }
}

// Decode edges once (int64/int32 -> int2 staging) + degree/histogram
__global__ void decode_hist_kernel(const void* __restrict__ ei, const float* __restrict__ ew,
                                   const int* __restrict__ flag,
                                   float* __restrict__ deg, int* __restrict__ cnt,
                                   int2* __restrict__ stage, int E) {
    int e = blockIdx.x * blockDim.x + threadIdx.x;
    if (e >= E) return;
    int is64 = *flag;
    int r = eidx(ei, is64, e);
    int c = eidx(ei, is64, E + e);
    stage[e] = make_int2(r, c);
    atomicAdd(&deg[c], ew[e]);
    atomicAdd(&cnt[c], 1);
}

// Block scan of cnt (exclusive) + dinv computation fused
__global__ void scan_block_kernel(const int* __restrict__ cnt, int* __restrict__ rowptr,
                                  int* __restrict__ bsum, float* __restrict__ deg, int N) {
    __shared__ int s[1024];
    int i = blockIdx.x * 1024 + threadIdx.x;
    int v = (i < N) ? cnt[i] : 0;
    s[threadIdx.x] = v;
    __syncthreads();
    for (int off = 1; off < 1024; off <<= 1) {
        int t = (threadIdx.x >= off) ? s[threadIdx.x - off] : 0;
        __syncthreads();
        s[threadIdx.x] += t;
        __syncthreads();
    }
    if (i < N) {
        rowptr[i] = s[threadIdx.x] - v;
        float d = deg[i] + 1.0f;
        deg[i] = (d > 0.f) ? rsqrtf(d) : 0.f;
    }
    if (threadIdx.x == 1023) bsum[blockIdx.x] = s[1023];
}

// Parallel scan of <=128 block sums
__global__ void scan_sums_kernel(int* __restrict__ bsum, int nblk) {
    __shared__ int s[128];
    int t = threadIdx.x;
    int v = (t < nblk) ? bsum[t] : 0;
    s[t] = v;
    __syncthreads();
    for (int off = 1; off < 128; off <<= 1) {
        int u = (t >= off) ? s[t - off] : 0;
        __syncthreads();
        s[t] += u;
        __syncthreads();
    }
    if (t < nblk) bsum[t] = s[t] - v;   // exclusive
}

__global__ void add_off_kernel(int* __restrict__ rowptr, const int* __restrict__ bsum,
                               int* __restrict__ cnt, int N, int E) {
    int i = blockIdx.x * blockDim.x + threadIdx.x;
    if (i < N) { rowptr[i] += bsum[i >> 10]; cnt[i] = 0; }
    if (i == 0) rowptr[N] = E;
}

__global__ void place_kernel(const int2* __restrict__ stage, const float* __restrict__ ew,
                             const float* __restrict__ dinv,
                             const int* __restrict__ rowptr, int* __restrict__ cnt,
                             int2* __restrict__ epack, int E) {
    int e = blockIdx.x * blockDim.x + threadIdx.x;
    if (e >= E) return;
    int2 rc = stage[e];
    int pos = rowptr[rc.y] + atomicAdd(&cnt[rc.y], 1);
    float nv = dinv[rc.x] * ew[e] * dinv[rc.y];
    epack[pos] = make_int2(rc.x, __float_as_int(nv));
}

// ---------------------------------------------------------------------------
// W prep (both layers in one launch): W^T split into bf16 hi/lo.
__global__ void wprep_kernel(const float* __restrict__ Wa, const float* __restrict__ Wb,
                             unsigned short* __restrict__ hiA, unsigned short* __restrict__ loA,
                             unsigned short* __restrict__ hiB, unsigned short* __restrict__ loB) {
    int b = blockIdx.x;
    const float* W = (b < 64) ? Wa : Wb;
    unsigned short* hi = (b < 64) ? hiA : hiB;
    unsigned short* lo = (b < 64) ? loA : loB;
    int idx = (b & 63) * 256 + threadIdx.x;
    int n = idx & 127, k = idx >> 7;
    float v = W[k * DIM + n];
    __nv_bfloat16 h = __float2bfloat16(v);
    __nv_bfloat16 l = __float2bfloat16(v - __bfloat162float(h));
    hi[n * DIM + k] = __bfloat16_as_ushort(h);
    lo[n * DIM + k] = __bfloat16_as_ushort(l);
}

// ---------------------------------------------------------------------------
// Shared GEMM machinery (mma.sync m16n8k16 bf16, split-bf16 3-pass).
#define SP_U32 68                       // row stride in uint32 (136 bf16)
#define MAT_BYTES (128 * SP_U32 * 4)    // 34816
#define TC_SMEM (4 * MAT_BYTES)         // 139264

__device__ __forceinline__ void mma_bf16(float* c, uint32_t a0, uint32_t a1,
                                         uint32_t a2, uint32_t a3,
                                         uint32_t b0, uint32_t b1) {
    asm volatile(
        "mma.sync.aligned.m16n8k16.row.col.f32.bf16.bf16.f32 "
        "{%0,%1,%2,%3}, {%4,%5,%6,%7}, {%8,%9}, {%0,%1,%2,%3};"
        : "+f"(c[0]), "+f"(c[1]), "+f"(c[2]), "+f"(c[3])
        : "r"(a0), "r"(a1), "r"(a2), "r"(a3), "r"(b0), "r"(b1));
}

// Split float4 -> two bf16x2 hi words + two lo words
__device__ __forceinline__ void split4(float4 v, uint2& hv, uint2& lv) {
    __nv_bfloat16 h0 = __float2bfloat16(v.x), h1 = __float2bfloat16(v.y);
    __nv_bfloat16 h2 = __float2bfloat16(v.z), h3 = __float2bfloat16(v.w);
    __nv_bfloat16 l0 = __float2bfloat16(v.x - __bfloat162float(h0));
    __nv_bfloat16 l1 = __float2bfloat16(v.y - __bfloat162float(h1));
    __nv_bfloat16 l2 = __float2bfloat16(v.z - __bfloat162float(h2));
    __nv_bfloat16 l3 = __float2bfloat16(v.w - __bfloat162float(h3));
    hv.x = (uint32_t)__bfloat16_as_ushort(h0) | ((uint32_t)__bfloat16_as_ushort(h1) << 16);
    hv.y = (uint32_t)__bfloat16_as_ushort(h2) | ((uint32_t)__bfloat16_as_ushort(h3) << 16);
    lv.x = (uint32_t)__bfloat16_as_ushort(l0) | ((uint32_t)__bfloat16_as_ushort(l1) << 16);
    lv.y = (uint32_t)__bfloat16_as_ushort(l2) | ((uint32_t)__bfloat16_as_ushort(l3) << 16);
}

// MMA mainloop + fp16 epilogue (A/B tiles already staged in smem)
__device__ __forceinline__ void mma_and_store(const uint32_t* sAh, const uint32_t* sAl,
                                              const uint32_t* sBh, const uint32_t* sBl,
                                              __half* __restrict__ C,
                                              int row0, int wid, int lane, int M) {
    float acc[16][4];
    #pragma unroll
    for (int t = 0; t < 16; t++) {
        acc[t][0] = 0.f; acc[t][1] = 0.f; acc[t][2] = 0.f; acc[t][3] = 0.f;
    }
    int l4 = lane >> 2, lm = lane & 3;
    int m0 = wid << 4;
    for (int p = 0; p < 3; p++) {            // hi*hi, hi*lo(B), lo(A)*hi
        const uint32_t* Ap = (p == 2) ? sAl : sAh;
        const uint32_t* Bp = (p == 1) ? sBl : sBh;
        #pragma unroll
        for (int ks = 0; ks < 8; ks++) {
            int ku = ks * 8 + lm;
            int au = (m0 + l4) * SP_U32 + ku;
            uint32_t a0 = Ap[au];
            uint32_t a1 = Ap[au + 8 * SP_U32];
            uint32_t a2 = Ap[au + 4];
            uint32_t a3 = Ap[au + 8 * SP_U32 + 4];
            #pragma unroll
            for (int nt = 0; nt < 16; nt++) {
                int bu = (nt * 8 + l4) * SP_U32 + ku;
                mma_bf16(acc[nt], a0, a1, a2, a3, Bp[bu], Bp[bu + 4]);
            }
        }
    }
    int r_lo = row0 + m0 + l4;
    int r_hi = r_lo + 8;
    #pragma unroll
    for (int nt = 0; nt < 16; nt++) {
        int col = nt * 8 + lm * 2;
        if (r_lo < M)
            *(__half2*)&C[(size_t)r_lo * 128 + col] =
                __float22half2_rn(make_float2(acc[nt][0], acc[nt][1]));
        if (r_hi < M)
            *(__half2*)&C[(size_t)r_hi * 128 + col] =
                __float22half2_rn(make_float2(acc[nt][2], acc[nt][3]));
    }
}

// ---------------------------------------------------------------------------
// Layer-1 GEMM: H1h[M,128] = x[M,128] @ W1 (fp32 input)
__global__ void __launch_bounds__(256) tcmm_kernel(const float4* __restrict__ A,
                                                   const uint32_t* __restrict__ Whi,
                                                   const uint32_t* __restrict__ Wlo,
                                                   __half* __restrict__ C, int M) {
    extern __shared__ char smc[];
    uint32_t* sAh = (uint32_t*)smc;
    uint32_t* sAl = (uint32_t*)(smc + MAT_BYTES);
    uint32_t* sBh = (uint32_t*)(smc + 2 * MAT_BYTES);
    uint32_t* sBl = (uint32_t*)(smc + 3 * MAT_BYTES);
    int tid = threadIdx.x, wid = tid >> 5, lane = tid & 31;
    int row0 = blockIdx.x << 7;

    #pragma unroll
    for (int i = tid; i < 8192; i += 256) {
        int r = i >> 6, c = i & 63;
        sBh[r * SP_U32 + c] = Whi[i];
        sBl[r * SP_U32 + c] = Wlo[i];
    }
    #pragma unroll
    for (int i = tid; i < 4096; i += 256) {
        int row = i >> 5, c4 = i & 31;
        int gr = row0 + row;
        float4 v = make_float4(0.f, 0.f, 0.f, 0.f);
        if (gr < M) v = A[gr * 32 + c4];
        uint2 hv, lv;
        split4(v, hv, lv);
        int o = row * SP_U32 + c4 * 2;
        *(uint2*)&sAh[o] = hv;
        *(uint2*)&sAl[o] = lv;
    }
    __syncthreads();
    mma_and_store(sAh, sAl, sBh, sBl, C, row0, wid, lane, M);
}

// ---------------------------------------------------------------------------
// Fused layer boundary: per-CTA SpMM over its 128 nodes (gather H1h, +b1, ReLU)
// -> bf16 split A tile in smem -> GEMM with W2 -> H2h fp16.
__global__ void __launch_bounds__(256) fused_spmm_gemm(const uint2* __restrict__ Hh,
                                                       const float* __restrict__ dinv,
                                                       const int* __restrict__ rowptr,
                                                       const int2* __restrict__ epack,
                                                       const float* __restrict__ bias,
                                                       const uint32_t* __restrict__ Whi,
                                                       const uint32_t* __restrict__ Wlo,
                                                       __half* __restrict__ C, int M) {
    extern __shared__ char smc[];
    uint32_t* sAh = (uint32_t*)smc;
    uint32_t* sAl = (uint32_t*)(smc + MAT_BYTES);
    uint32_t* sBh = (uint32_t*)(smc + 2 * MAT_BYTES);
    uint32_t* sBl = (uint32_t*)(smc + 3 * MAT_BYTES);
    int tid = threadIdx.x, wid = tid >> 5, lane = tid & 31;
    int row0 = blockIdx.x << 7;

    #pragma unroll
    for (int i = tid; i < 8192; i += 256) {
        int r = i >> 6, c = i & 63;
        sBh[r * SP_U32 + c] = Whi[i];
        sBl[r * SP_U32 + c] = Wlo[i];
    }

    // SpMM phase: warp handles 16 consecutive rows of the tile
    float4 bb = __ldg(&((const float4*)bias)[lane]);
    for (int j = 0; j < 16; j++) {
        int trow = (wid << 4) + j;
        int gw = row0 + trow;
        float4 acc = make_float4(0.f, 0.f, 0.f, 0.f);
        if (gw < M) {
            float di = __ldg(&dinv[gw]);
            float s = di * di;
            uint2 hv = __ldg(&Hh[(size_t)gw * 32 + lane]);
            float2 h0 = __half22float2(*(__half2*)&hv.x);
            float2 h1 = __half22float2(*(__half2*)&hv.y);
            acc = make_float4(s * h0.x, s * h0.y, s * h1.x, s * h1.y);
            int beg = __ldg(&rowptr[gw]), end = __ldg(&rowptr[gw + 1]);
            #pragma unroll 4
            for (int i = beg; i < end; i++) {
                int2 e = __ldg(&epack[i]);
                float w = __int_as_float(e.y);
                uint2 v = __ldg(&Hh[(size_t)e.x * 32 + lane]);
                float2 f0 = __half22float2(*(__half2*)&v.x);
                float2 f1 = __half22float2(*(__half2*)&v.y);
                acc.x += w * f0.x; acc.y += w * f0.y;
                acc.z += w * f1.x; acc.w += w * f1.y;
            }
            acc.x = fmaxf(acc.x + bb.x, 0.f);
            acc.y = fmaxf(acc.y + bb.y, 0.f);
            acc.z = fmaxf(acc.z + bb.z, 0.f);
            acc.w = fmaxf(acc.w + bb.w, 0.f);
        }
        uint2 hv, lv;
        split4(acc, hv, lv);
        int o = trow * SP_U32 + lane * 2;
        *(uint2*)&sAh[o] = hv;
        *(uint2*)&sAl[o] = lv;
    }
    __syncthreads();
    mma_and_store(sAh, sAl, sBh, sBl, C, row0, wid, lane, M);
}

// ---------------------------------------------------------------------------
// Final SpMM: gather H2h, +b2, ReLU, fp32 output
__global__ void __launch_bounds__(256) spmm_kernel(const uint2* __restrict__ Hh,
                                                   const float* __restrict__ dinv,
                                                   const int* __restrict__ rowptr,
                                                   const int2* __restrict__ epack,
                                                   const float* __restrict__ bias,
                                                   float* __restrict__ Out, int N) {
    int gw = (blockIdx.x * blockDim.x + threadIdx.x) >> 5;
    int lane = threadIdx.x & 31;
    if (gw >= N) return;
    float di = __ldg(&dinv[gw]);
    float s = di * di;
    uint2 hv = __ldg(&Hh[(size_t)gw * 32 + lane]);
    float2 h0 = __half22float2(*(__half2*)&hv.x);
    float2 h1 = __half22float2(*(__half2*)&hv.y);
    float4 acc = make_float4(s * h0.x, s * h0.y, s * h1.x, s * h1.y);
    int beg = __ldg(&rowptr[gw]), end = __ldg(&rowptr[gw + 1]);
    #pragma unroll 4
    for (int i = beg; i < end; i++) {
        int2 e = __ldg(&epack[i]);
        float w = __int_as_float(e.y);
        uint2 v = __ldg(&Hh[(size_t)e.x * 32 + lane]);
        float2 f0 = __half22float2(*(__half2*)&v.x);
        float2 f1 = __half22float2(*(__half2*)&v.y);
        acc.x += w * f0.x; acc.y += w * f0.y;
        acc.z += w * f1.x; acc.w += w * f1.y;
    }
    float4 bb = __ldg(&((const float4*)bias)[lane]);
    float4 o;
    o.x = fmaxf(acc.x + bb.x, 0.f);
    o.y = fmaxf(acc.y + bb.y, 0.f);
    o.z = fmaxf(acc.z + bb.z, 0.f);
    o.w = fmaxf(acc.w + bb.w, 0.f);
    ((float4*)Out)[(size_t)gw * 32 + lane] = o;
}

// ---------------------------------------------------------------------------
extern "C" void kernel_launch(void* const* d_in, const int* in_sizes, int n_in,
                              void* d_out, int out_size) {
    const float* x  = (const float*)d_in[0];
    const void*  ei = d_in[1];
    const float* ew = (const float*)d_in[2];
    const float* W1 = (const float*)d_in[3];
    const float* b1 = (const float*)d_in[4];
    const float* W2 = (const float*)d_in[5];
    const float* b2 = (const float*)d_in[6];
    float* out = (float*)d_out;

    int N = in_sizes[0] / DIM;
    int E = in_sizes[2];

    float* deg;
    __half *H1h, *H2h;
    int *cnt, *rowptr, *bsum, *flag;
    int2 *stage, *epack;
    unsigned short *w1h, *w1l, *w2h, *w2l;
    cudaGetSymbolAddress((void**)&deg,    g_dinv);
    cudaGetSymbolAddress((void**)&cnt,    g_cnt);
    cudaGetSymbolAddress((void**)&rowptr, g_rowptr);
    cudaGetSymbolAddress((void**)&bsum,   g_bsum);
    cudaGetSymbolAddress((void**)&flag,   g_is64);
    cudaGetSymbolAddress((void**)&stage,  g_stage);
    cudaGetSymbolAddress((void**)&epack,  g_edge);
    cudaGetSymbolAddress((void**)&H1h,    g_H1h);
    cudaGetSymbolAddress((void**)&H2h,    g_H2h);
    cudaGetSymbolAddress((void**)&w1h,    g_W1hi);
    cudaGetSymbolAddress((void**)&w1l,    g_W1lo);
    cudaGetSymbolAddress((void**)&w2h,    g_W2hi);
    cudaGetSymbolAddress((void**)&w2l,    g_W2lo);

    cudaFuncSetAttribute(tcmm_kernel, cudaFuncAttributeMaxDynamicSharedMemorySize, TC_SMEM);
    cudaFuncSetAttribute(fused_spmm_gemm, cudaFuncAttributeMaxDynamicSharedMemorySize, TC_SMEM);

    int eb = (E + 255) / 256;
    int nb = (N + 255) / 256;
    int nblk = (N + 1023) / 1024;
    int mmb = (N + 127) / 128;
    int spb = (N * 32 + 255) / 256;

    // Fork: branch B (dense path) runs concurrently with branch A (CSR build)
    cudaStream_t s2;
    cudaStreamCreateWithFlags(&s2, cudaStreamNonBlocking);
    cudaEvent_t evRoot, evB;
    cudaEventCreateWithFlags(&evRoot, cudaEventDisableTiming);
    cudaEventCreateWithFlags(&evB, cudaEventDisableTiming);

    cudaEventRecord(evRoot, 0);
    cudaStreamWaitEvent(s2, evRoot, 0);

    // Branch B: W prep + layer-1 GEMM (depends only on x, W1, W2)
    wprep_kernel<<<128, 256, 0, s2>>>(W1, W2, w1h, w1l, w2h, w2l);
    tcmm_kernel<<<mmb, 256, TC_SMEM, s2>>>((const float4*)x, (const uint32_t*)w1h,
                                           (const uint32_t*)w1l, H1h, N);
    cudaEventRecord(evB, s2);

    // Branch A: CSR build
    zero_probe_kernel<<<nb, 256>>>(deg, cnt, N, (const long long*)ei, flag);
    decode_hist_kernel<<<eb, 256>>>(ei, ew, flag, deg, cnt, stage, E);
    scan_block_kernel<<<nblk, 1024>>>(cnt, rowptr, bsum, deg, N);
    scan_sums_kernel<<<1, 128>>>(bsum, nblk);
    add_off_kernel<<<nb, 256>>>(rowptr, bsum, cnt, N, E);
    place_kernel<<<eb, 256>>>(stage, ew, deg, rowptr, cnt, epack, E);

    // Join, then fused layer boundary + final SpMM
    cudaStreamWaitEvent(0, evB, 0);
    fused_spmm_gemm<<<mmb, 256, TC_SMEM>>>((const uint2*)H1h, deg, rowptr, epack, b1,
                                           (const uint32_t*)w2h, (const uint32_t*)w2l, H2h, N);
    spmm_kernel<<<spb, 256>>>((const uint2*)H2h, deg, rowptr, epack, b2, out, N);

    cudaEventDestroy(evRoot);
    cudaEventDestroy(evB);
    cudaStreamDestroy(s2);
}

// round 12
// speedup vs baseline: 1.1214x; 1.1214x over previous
#include <cuda_runtime.h>
#include <cuda_bf16.h>
#include <cuda_fp16.h>
#include <cstdint>

#define N_MAX 100000
#define E_MAX 1600000
#define DIM 128

// ---------------------------------------------------------------------------
// Static scratch
__device__ float g_dinv[N_MAX];
__device__ int   g_cnt[N_MAX];
__device__ int   g_rowptr[N_MAX + 1];
__device__ int   g_bsum[128];
__device__ int   g_is64;
__device__ int2  g_stage[E_MAX];         // decoded {row, col}
__device__ int2  g_edge[E_MAX];          // CSR packed {src, norm-as-int}
__device__ __half g_Hh[N_MAX * DIM];     // post-GEMM features (fp16)
__device__ float  g_Z[N_MAX * DIM];      // layer-1 output (fp32)
// bf16 W^T images (hi/lo split), element (n,k) at offset n*128+k
__device__ unsigned short g_W1hi[DIM * DIM], g_W1lo[DIM * DIM];
__device__ unsigned short g_W2hi[DIM * DIM], g_W2lo[DIM * DIM];

// ---------------------------------------------------------------------------
__device__ __forceinline__ int eidx(const void* ei, int is64, int p) {
    return is64 ? (int)((const long long*)ei)[p] : ((const int*)ei)[p];
}

// Zero + dtype probe fused
__global__ void zero_probe_kernel(float* __restrict__ deg, int* __restrict__ cnt,
                                  int N, const long long* __restrict__ ei,
                                  int* __restrict__ flag) {
    int i = blockIdx.x * blockDim.x + threadIdx.x;
    if (i < N) { deg[i] = 0.f; cnt[i] = 0; }
    if (blockIdx.x == 0 && threadIdx.x == 0) {
        int ok = 1;
        for (int j = 0; j < 64; j++) {
            long long v = ei[j];
            if (v < 0 || v >= (long long)N) { ok = 0; break; }
        }
        *flag = ok;
    }
}

// Decode edges once (int64/int32 -> int2 staging) + degree/histogram
__global__ void decode_hist_kernel(const void* __restrict__ ei, const float* __restrict__ ew,
                                   const int* __restrict__ flag,
                                   float* __restrict__ deg, int* __restrict__ cnt,
                                   int2* __restrict__ stage, int E) {
    int e = blockIdx.x * blockDim.x + threadIdx.x;
    if (e >= E) return;
    int is64 = *flag;
    int r = eidx(ei, is64, e);
    int c = eidx(ei, is64, E + e);
    stage[e] = make_int2(r, c);
    atomicAdd(&deg[c], ew[e]);
    atomicAdd(&cnt[c], 1);
}

// Block scan of cnt (exclusive) + dinv computation fused
__global__ void scan_block_kernel(const int* __restrict__ cnt, int* __restrict__ rowptr,
                                  int* __restrict__ bsum, float* __restrict__ deg, int N) {
    __shared__ int s[1024];
    int i = blockIdx.x * 1024 + threadIdx.x;
    int v = (i < N) ? cnt[i] : 0;
    s[threadIdx.x] = v;
    __syncthreads();
    for (int off = 1; off < 1024; off <<= 1) {
        int t = (threadIdx.x >= off) ? s[threadIdx.x - off] : 0;
        __syncthreads();
        s[threadIdx.x] += t;
        __syncthreads();
    }
    if (i < N) {
        rowptr[i] = s[threadIdx.x] - v;
        float d = deg[i] + 1.0f;
        deg[i] = (d > 0.f) ? rsqrtf(d) : 0.f;
    }
    if (threadIdx.x == 1023) bsum[blockIdx.x] = s[1023];
}

// Parallel scan of <=128 block sums
__global__ void scan_sums_kernel(int* __restrict__ bsum, int nblk) {
    __shared__ int s[128];
    int t = threadIdx.x;
    int v = (t < nblk) ? bsum[t] : 0;
    s[t] = v;
    __syncthreads();
    for (int off = 1; off < 128; off <<= 1) {
        int u = (t >= off) ? s[t - off] : 0;
        __syncthreads();
        s[t] += u;
        __syncthreads();
    }
    if (t < nblk) bsum[t] = s[t] - v;   // exclusive
}

__global__ void add_off_kernel(int* __restrict__ rowptr, const int* __restrict__ bsum,
                               int* __restrict__ cnt, int N, int E) {
    int i = blockIdx.x * blockDim.x + threadIdx.x;
    if (i < N) { rowptr[i] += bsum[i >> 10]; cnt[i] = 0; }
    if (i == 0) rowptr[N] = E;
}

__global__ void place_kernel(const int2* __restrict__ stage, const float* __restrict__ ew,
                             const float* __restrict__ dinv,
                             const int* __restrict__ rowptr, int* __restrict__ cnt,
                             int2* __restrict__ epack, int E) {
    int e = blockIdx.x * blockDim.x + threadIdx.x;
    if (e >= E) return;
    int2 rc = stage[e];
    int pos = rowptr[rc.y] + atomicAdd(&cnt[rc.y], 1);
    float nv = dinv[rc.x] * ew[e] * dinv[rc.y];
    epack[pos] = make_int2(rc.x, __float_as_int(nv));
}

// ---------------------------------------------------------------------------
// W prep (both layers in one launch): W^T split into bf16 hi/lo.
__global__ void wprep_kernel(const float* __restrict__ Wa, const float* __restrict__ Wb,
                             unsigned short* __restrict__ hiA, unsigned short* __restrict__ loA,
                             unsigned short* __restrict__ hiB, unsigned short* __restrict__ loB) {
    int b = blockIdx.x;
    const float* W = (b < 64) ? Wa : Wb;
    unsigned short* hi = (b < 64) ? hiA : hiB;
    unsigned short* lo = (b < 64) ? loA : loB;
    int idx = (b & 63) * 256 + threadIdx.x;
    int n = idx & 127, k = idx >> 7;
    float v = W[k * DIM + n];
    __nv_bfloat16 h = __float2bfloat16(v);
    __nv_bfloat16 l = __float2bfloat16(v - __bfloat162float(h));
    hi[n * DIM + k] = __bfloat16_as_ushort(h);
    lo[n * DIM + k] = __bfloat16_as_ushort(l);
}

// ---------------------------------------------------------------------------
// Tensor-core GEMM via mma.sync (m16n8k16 bf16), split-bf16 3-pass.
#define SP_U32 68                       // row stride in uint32 (136 bf16)
#define MAT_BYTES (128 * SP_U32 * 4)    // 34816
#define TC_SMEM (4 * MAT_BYTES)         // 139264

__device__ __forceinline__ void mma_bf16(float* c, uint32_t a0, uint32_t a1,
                                         uint32_t a2, uint32_t a3,
                                         uint32_t b0, uint32_t b1) {
    asm volatile(
        "mma.sync.aligned.m16n8k16.row.col.f32.bf16.bf16.f32 "
        "{%0,%1,%2,%3}, {%4,%5,%6,%7}, {%8,%9}, {%0,%1,%2,%3};"
        : "+f"(c[0]), "+f"(c[1]), "+f"(c[2]), "+f"(c[3])
        : "r"(a0), "r"(a1), "r"(a2), "r"(a3), "r"(b0), "r"(b1));
}

__device__ __forceinline__ void split4(float4 v, uint2& hv, uint2& lv) {
    __nv_bfloat16 h0 = __float2bfloat16(v.x), h1 = __float2bfloat16(v.y);
    __nv_bfloat16 h2 = __float2bfloat16(v.z), h3 = __float2bfloat16(v.w);
    __nv_bfloat16 l0 = __float2bfloat16(v.x - __bfloat162float(h0));
    __nv_bfloat16 l1 = __float2bfloat16(v.y - __bfloat162float(h1));
    __nv_bfloat16 l2 = __float2bfloat16(v.z - __bfloat162float(h2));
    __nv_bfloat16 l3 = __float2bfloat16(v.w - __bfloat162float(h3));
    hv.x = (uint32_t)__bfloat16_as_ushort(h0) | ((uint32_t)__bfloat16_as_ushort(h1) << 16);
    hv.y = (uint32_t)__bfloat16_as_ushort(h2) | ((uint32_t)__bfloat16_as_ushort(h3) << 16);
    lv.x = (uint32_t)__bfloat16_as_ushort(l0) | ((uint32_t)__bfloat16_as_ushort(l1) << 16);
    lv.y = (uint32_t)__bfloat16_as_ushort(l2) | ((uint32_t)__bfloat16_as_ushort(l3) << 16);
}

__global__ void __launch_bounds__(256) tcmm_kernel(const float4* __restrict__ A,
                                                   const uint32_t* __restrict__ Whi,
                                                   const uint32_t* __restrict__ Wlo,
                                                   __half* __restrict__ C, int M) {
    extern __shared__ char smc[];
    uint32_t* sAh = (uint32_t*)smc;
    uint32_t* sAl = (uint32_t*)(smc + MAT_BYTES);
    uint32_t* sBh = (uint32_t*)(smc + 2 * MAT_BYTES);
    uint32_t* sBl = (uint32_t*)(smc + 3 * MAT_BYTES);
    int tid = threadIdx.x, wid = tid >> 5, lane = tid & 31;
    int row0 = blockIdx.x << 7;

    #pragma unroll
    for (int i = tid; i < 8192; i += 256) {
        int r = i >> 6, c = i & 63;
        sBh[r * SP_U32 + c] = Whi[i];
        sBl[r * SP_U32 + c] = Wlo[i];
    }
    #pragma unroll
    for (int i = tid; i < 4096; i += 256) {
        int row = i >> 5, c4 = i & 31;
        int gr = row0 + row;
        float4 v = make_float4(0.f, 0.f, 0.f, 0.f);
        if (gr < M) v = A[gr * 32 + c4];
        uint2 hv, lv;
        split4(v, hv, lv);
        int o = row * SP_U32 + c4 * 2;
        *(uint2*)&sAh[o] = hv;
        *(uint2*)&sAl[o] = lv;
    }
    __syncthreads();

    float acc[16][4];
    #pragma unroll
    for (int t = 0; t < 16; t++) {
        acc[t][0] = 0.f; acc[t][1] = 0.f; acc[t][2] = 0.f; acc[t][3] = 0.f;
    }
    int l4 = lane >> 2, lm = lane & 3;
    int m0 = wid << 4;
    for (int p = 0; p < 3; p++) {            // hi*hi, hi*lo(B), lo(A)*hi
        const uint32_t* Ap = (p == 2) ? sAl : sAh;
        const uint32_t* Bp = (p == 1) ? sBl : sBh;
        #pragma unroll
        for (int ks = 0; ks < 8; ks++) {
            int ku = ks * 8 + lm;
            int au = (m0 + l4) * SP_U32 + ku;
            uint32_t a0 = Ap[au];
            uint32_t a1 = Ap[au + 8 * SP_U32];
            uint32_t a2 = Ap[au + 4];
            uint32_t a3 = Ap[au + 8 * SP_U32 + 4];
            #pragma unroll
            for (int nt = 0; nt < 16; nt++) {
                int bu = (nt * 8 + l4) * SP_U32 + ku;
                mma_bf16(acc[nt], a0, a1, a2, a3, Bp[bu], Bp[bu + 4]);
            }
        }
    }

    int r_lo = row0 + m0 + l4;
    int r_hi = r_lo + 8;
    #pragma unroll
    for (int nt = 0; nt < 16; nt++) {
        int col = nt * 8 + lm * 2;
        if (r_lo < M)
            *(__half2*)&C[(size_t)r_lo * 128 + col] =
                __float22half2_rn(make_float2(acc[nt][0], acc[nt][1]));
        if (r_hi < M)
            *(__half2*)&C[(size_t)r_hi * 128 + col] =
                __float22half2_rn(make_float2(acc[nt][2], acc[nt][3]));
    }
}

// ---------------------------------------------------------------------------
// Gather-based SpMM on fp16 features, fp32 accumulation, full occupancy.
__global__ void __launch_bounds__(256) spmm_kernel(const uint2* __restrict__ Hh,
                                                   const float* __restrict__ dinv,
                                                   const int* __restrict__ rowptr,
                                                   const int2* __restrict__ epack,
                                                   const float* __restrict__ bias,
                                                   float* __restrict__ Out, int N) {
    int gw = (blockIdx.x * blockDim.x + threadIdx.x) >> 5;
    int lane = threadIdx.x & 31;
    if (gw >= N) return;
    float di = __ldg(&dinv[gw]);
    float s = di * di;
    uint2 hv = __ldg(&Hh[(size_t)gw * 32 + lane]);
    float2 h0 = __half22float2(*(__half2*)&hv.x);
    float2 h1 = __half22float2(*(__half2*)&hv.y);
    float4 acc = make_float4(s * h0.x, s * h0.y, s * h1.x, s * h1.y);
    int beg = __ldg(&rowptr[gw]), end = __ldg(&rowptr[gw + 1]);
    #pragma unroll 4
    for (int i = beg; i < end; i++) {
        int2 e = __ldg(&epack[i]);
        float w = __int_as_float(e.y);
        uint2 v = __ldg(&Hh[(size_t)e.x * 32 + lane]);
        float2 f0 = __half22float2(*(__half2*)&v.x);
        float2 f1 = __half22float2(*(__half2*)&v.y);
        acc.x += w * f0.x; acc.y += w * f0.y;
        acc.z += w * f1.x; acc.w += w * f1.y;
    }
    float4 bb = __ldg(&((const float4*)bias)[lane]);
    float4 o;
    o.x = fmaxf(acc.x + bb.x, 0.f);
    o.y = fmaxf(acc.y + bb.y, 0.f);
    o.z = fmaxf(acc.z + bb.z, 0.f);
    o.w = fmaxf(acc.w + bb.w, 0.f);
    ((float4*)Out)[(size_t)gw * 32 + lane] = o;
}

// ---------------------------------------------------------------------------
extern "C" void kernel_launch(void* const* d_in, const int* in_sizes, int n_in,
                              void* d_out, int out_size) {
    const float* x  = (const float*)d_in[0];
    const void*  ei = d_in[1];
    const float* ew = (const float*)d_in[2];
    const float* W1 = (const float*)d_in[3];
    const float* b1 = (const float*)d_in[4];
    const float* W2 = (const float*)d_in[5];
    const float* b2 = (const float*)d_in[6];
    float* out = (float*)d_out;

    int N = in_sizes[0] / DIM;
    int E = in_sizes[2];

    float *deg, *Z;
    __half* Hh;
    int *cnt, *rowptr, *bsum, *flag;
    int2 *stage, *epack;
    unsigned short *w1h, *w1l, *w2h, *w2l;
    cudaGetSymbolAddress((void**)&deg,    g_dinv);
    cudaGetSymbolAddress((void**)&cnt,    g_cnt);
    cudaGetSymbolAddress((void**)&rowptr, g_rowptr);
    cudaGetSymbolAddress((void**)&bsum,   g_bsum);
    cudaGetSymbolAddress((void**)&flag,   g_is64);
    cudaGetSymbolAddress((void**)&stage,  g_stage);
    cudaGetSymbolAddress((void**)&epack,  g_edge);
    cudaGetSymbolAddress((void**)&Hh,     g_Hh);
    cudaGetSymbolAddress((void**)&Z,      g_Z);
    cudaGetSymbolAddress((void**)&w1h,    g_W1hi);
    cudaGetSymbolAddress((void**)&w1l,    g_W1lo);
    cudaGetSymbolAddress((void**)&w2h,    g_W2hi);
    cudaGetSymbolAddress((void**)&w2l,    g_W2lo);

    cudaFuncSetAttribute(tcmm_kernel, cudaFuncAttributeMaxDynamicSharedMemorySize, TC_SMEM);

    int eb = (E + 255) / 256;
    int nb = (N + 255) / 256;
    int nblk = (N + 1023) / 1024;
    int mmb = (N + 127) / 128;
    int spb = (N * 32 + 255) / 256;

    // Fork: dense prologue (W prep + layer-1 GEMM) overlaps the CSR build
    cudaStream_t s2;
    cudaStreamCreateWithFlags(&s2, cudaStreamNonBlocking);
    cudaEvent_t evRoot, evB;
    cudaEventCreateWithFlags(&evRoot, cudaEventDisableTiming);
    cudaEventCreateWithFlags(&evB, cudaEventDisableTiming);

    cudaEventRecord(evRoot, 0);
    cudaStreamWaitEvent(s2, evRoot, 0);

    // Branch B: dense path (depends only on x, W1, W2)
    wprep_kernel<<<128, 256, 0, s2>>>(W1, W2, w1h, w1l, w2h, w2l);
    tcmm_kernel<<<mmb, 256, TC_SMEM, s2>>>((const float4*)x, (const uint32_t*)w1h,
                                           (const uint32_t*)w1l, Hh, N);
    cudaEventRecord(evB, s2);

    // Branch A: CSR build
    zero_probe_kernel<<<nb, 256>>>(deg, cnt, N, (const long long*)ei, flag);
    decode_hist_kernel<<<eb, 256>>>(ei, ew, flag, deg, cnt, stage, E);
    scan_block_kernel<<<nblk, 1024>>>(cnt, rowptr, bsum, deg, N);
    scan_sums_kernel<<<1, 128>>>(bsum, nblk);
    add_off_kernel<<<nb, 256>>>(rowptr, bsum, cnt, N, E);
    place_kernel<<<eb, 256>>>(stage, ew, deg, rowptr, cnt, epack, E);

    // Join, then the serial tail at full occupancy
    cudaStreamWaitEvent(0, evB, 0);
    spmm_kernel<<<spb, 256>>>((const uint2*)Hh, deg, rowptr, epack, b1, Z, N);
    tcmm_kernel<<<mmb, 256, TC_SMEM>>>((const float4*)Z, (const uint32_t*)w2h,
                                       (const uint32_t*)w2l, Hh, N);
    spmm_kernel<<<spb, 256>>>((const uint2*)Hh, deg, rowptr, epack, b2, out, N);

    cudaEventDestroy(evRoot);
    cudaEventDestroy(evB);
    cudaStreamDestroy(s2);
}

// round 13
// speedup vs baseline: 1.5865x; 1.4148x over previous
#include <cuda_runtime.h>
#include <cuda_bf16.h>
#include <cuda_fp16.h>
#include <cstdint>

#define N_MAX 100000
#define E_MAX 1600000
#define DIM 128

// ---------------------------------------------------------------------------
// Static scratch
__device__ float g_dinv[N_MAX];
__device__ int   g_cnt[N_MAX];
__device__ int   g_rowptr[N_MAX + 1];
__device__ int   g_bsum[128];
__device__ int   g_is64;
__device__ int2  g_stage[E_MAX];         // decoded {row, col}
__device__ int2  g_edge[E_MAX];          // CSR packed {src, norm-as-int}
__device__ __half g_Hh[N_MAX * DIM];     // post-GEMM features (fp16)
__device__ __half g_Zh[N_MAX * DIM];     // layer-1 output (fp16)
// bf16 W^T images (hi/lo split), element (n,k) at offset n*128+k
__device__ unsigned short g_W1hi[DIM * DIM], g_W1lo[DIM * DIM];
__device__ unsigned short g_W2hi[DIM * DIM], g_W2lo[DIM * DIM];

// ---------------------------------------------------------------------------
__device__ __forceinline__ int eidx(const void* ei, int is64, int p) {
    return is64 ? (int)((const long long*)ei)[p] : ((const int*)ei)[p];
}

// Zero + dtype probe fused
__global__ void zero_probe_kernel(float* __restrict__ deg, int* __restrict__ cnt,
                                  int N, const long long* __restrict__ ei,
                                  int* __restrict__ flag) {
    int i = blockIdx.x * blockDim.x + threadIdx.x;
    if (i < N) { deg[i] = 0.f; cnt[i] = 0; }
    if (blockIdx.x == 0 && threadIdx.x == 0) {
        int ok = 1;
        for (int j = 0; j < 64; j++) {
            long long v = ei[j];
            if (v < 0 || v >= (long long)N) { ok = 0; break; }
        }
        *flag = ok;
    }
}

// Decode edges once (int64/int32 -> int2 staging) + degree/histogram
__global__ void decode_hist_kernel(const void* __restrict__ ei, const float* __restrict__ ew,
                                   const int* __restrict__ flag,
                                   float* __restrict__ deg, int* __restrict__ cnt,
                                   int2* __restrict__ stage, int E) {
    int e = blockIdx.x * blockDim.x + threadIdx.x;
    if (e >= E) return;
    int is64 = *flag;
    int r = eidx(ei, is64, e);
    int c = eidx(ei, is64, E + e);
    stage[e] = make_int2(r, c);
    atomicAdd(&deg[c], ew[e]);
    atomicAdd(&cnt[c], 1);
}

// Block scan of cnt (exclusive) + dinv computation fused
__global__ void scan_block_kernel(const int* __restrict__ cnt, int* __restrict__ rowptr,
                                  int* __restrict__ bsum, float* __restrict__ deg, int N) {
    __shared__ int s[1024];
    int i = blockIdx.x * 1024 + threadIdx.x;
    int v = (i < N) ? cnt[i] : 0;
    s[threadIdx.x] = v;
    __syncthreads();
    for (int off = 1; off < 1024; off <<= 1) {
        int t = (threadIdx.x >= off) ? s[threadIdx.x - off] : 0;
        __syncthreads();
        s[threadIdx.x] += t;
        __syncthreads();
    }
    if (i < N) {
        rowptr[i] = s[threadIdx.x] - v;
        float d = deg[i] + 1.0f;
        deg[i] = (d > 0.f) ? rsqrtf(d) : 0.f;
    }
    if (threadIdx.x == 1023) bsum[blockIdx.x] = s[1023];
}

// Parallel scan of <=128 block sums
__global__ void scan_sums_kernel(int* __restrict__ bsum, int nblk) {
    __shared__ int s[128];
    int t = threadIdx.x;
    int v = (t < nblk) ? bsum[t] : 0;
    s[t] = v;
    __syncthreads();
    for (int off = 1; off < 128; off <<= 1) {
        int u = (t >= off) ? s[t - off] : 0;
        __syncthreads();
        s[t] += u;
        __syncthreads();
    }
    if (t < nblk) bsum[t] = s[t] - v;   // exclusive
}

__global__ void add_off_kernel(int* __restrict__ rowptr, const int* __restrict__ bsum,
                               int* __restrict__ cnt, int N, int E) {
    int i = blockIdx.x * blockDim.x + threadIdx.x;
    if (i < N) { rowptr[i] += bsum[i >> 10]; cnt[i] = 0; }
    if (i == 0) rowptr[N] = E;
}

__global__ void place_kernel(const int2* __restrict__ stage, const float* __restrict__ ew,
                             const float* __restrict__ dinv,
                             const int* __restrict__ rowptr, int* __restrict__ cnt,
                             int2* __restrict__ epack, int E) {
    int e = blockIdx.x * blockDim.x + threadIdx.x;
    if (e >= E) return;
    int2 rc = stage[e];
    int pos = rowptr[rc.y] + atomicAdd(&cnt[rc.y], 1);
    float nv = dinv[rc.x] * ew[e] * dinv[rc.y];
    epack[pos] = make_int2(rc.x, __float_as_int(nv));
}

// ---------------------------------------------------------------------------
// W prep (both layers in one launch): W^T split into bf16 hi/lo.
__global__ void wprep_kernel(const float* __restrict__ Wa, const float* __restrict__ Wb,
                             unsigned short* __restrict__ hiA, unsigned short* __restrict__ loA,
                             unsigned short* __restrict__ hiB, unsigned short* __restrict__ loB) {
    int b = blockIdx.x;
    const float* W = (b < 64) ? Wa : Wb;
    unsigned short* hi = (b < 64) ? hiA : hiB;
    unsigned short* lo = (b < 64) ? loA : loB;
    int idx = (b & 63) * 256 + threadIdx.x;
    int n = idx & 127, k = idx >> 7;
    float v = W[k * DIM + n];
    __nv_bfloat16 h = __float2bfloat16(v);
    __nv_bfloat16 l = __float2bfloat16(v - __bfloat162float(h));
    hi[n * DIM + k] = __bfloat16_as_ushort(h);
    lo[n * DIM + k] = __bfloat16_as_ushort(l);
}

// ---------------------------------------------------------------------------
// Tensor-core GEMM via mma.sync (m16n8k16 bf16), split-bf16 3-pass.
#define SP_U32 68                       // row stride in uint32 (136 bf16)
#define MAT_BYTES (128 * SP_U32 * 4)    // 34816
#define TC_SMEM (4 * MAT_BYTES)         // 139264

__device__ __forceinline__ void mma_bf16(float* c, uint32_t a0, uint32_t a1,
                                         uint32_t a2, uint32_t a3,
                                         uint32_t b0, uint32_t b1) {
    asm volatile(
        "mma.sync.aligned.m16n8k16.row.col.f32.bf16.bf16.f32 "
        "{%0,%1,%2,%3}, {%4,%5,%6,%7}, {%8,%9}, {%0,%1,%2,%3};"
        : "+f"(c[0]), "+f"(c[1]), "+f"(c[2]), "+f"(c[3])
        : "r"(a0), "r"(a1), "r"(a2), "r"(a3), "r"(b0), "r"(b1));
}

__device__ __forceinline__ void split4(float4 v, uint2& hv, uint2& lv) {
    __nv_bfloat16 h0 = __float2bfloat16(v.x), h1 = __float2bfloat16(v.y);
    __nv_bfloat16 h2 = __float2bfloat16(v.z), h3 = __float2bfloat16(v.w);
    __nv_bfloat16 l0 = __float2bfloat16(v.x - __bfloat162float(h0));
    __nv_bfloat16 l1 = __float2bfloat16(v.y - __bfloat162float(h1));
    __nv_bfloat16 l2 = __float2bfloat16(v.z - __bfloat162float(h2));
    __nv_bfloat16 l3 = __float2bfloat16(v.w - __bfloat162float(h3));
    hv.x = (uint32_t)__bfloat16_as_ushort(h0) | ((uint32_t)__bfloat16_as_ushort(h1) << 16);
    hv.y = (uint32_t)__bfloat16_as_ushort(h2) | ((uint32_t)__bfloat16_as_ushort(h3) << 16);
    lv.x = (uint32_t)__bfloat16_as_ushort(l0) | ((uint32_t)__bfloat16_as_ushort(l1) << 16);
    lv.y = (uint32_t)__bfloat16_as_ushort(l2) | ((uint32_t)__bfloat16_as_ushort(l3) << 16);
}

// HALF_IN: A is fp16 (uint2 per 4 elems); else fp32 (float4)
template <bool HALF_IN>
__global__ void __launch_bounds__(256) tcmm_kernel(const void* __restrict__ A,
                                                   const uint32_t* __restrict__ Whi,
                                                   const uint32_t* __restrict__ Wlo,
                                                   __half* __restrict__ C, int M) {
    extern __shared__ char smc[];
    uint32_t* sAh = (uint32_t*)smc;
    uint32_t* sAl = (uint32_t*)(smc + MAT_BYTES);
    uint32_t* sBh = (uint32_t*)(smc + 2 * MAT_BYTES);
    uint32_t* sBl = (uint32_t*)(smc + 3 * MAT_BYTES);
    int tid = threadIdx.x, wid = tid >> 5, lane = tid & 31;
    int row0 = blockIdx.x << 7;

    #pragma unroll
    for (int i = tid; i < 8192; i += 256) {
        int r = i >> 6, c = i & 63;
        sBh[r * SP_U32 + c] = Whi[i];
        sBl[r * SP_U32 + c] = Wlo[i];
    }
    #pragma unroll
    for (int i = tid; i < 4096; i += 256) {
        int row = i >> 5, c4 = i & 31;
        int gr = row0 + row;
        float4 v = make_float4(0.f, 0.f, 0.f, 0.f);
        if (gr < M) {
            if (HALF_IN) {
                uint2 u = ((const uint2*)A)[(size_t)gr * 32 + c4];
                float2 a = __half22float2(*(__half2*)&u.x);
                float2 b = __half22float2(*(__half2*)&u.y);
                v = make_float4(a.x, a.y, b.x, b.y);
            } else {
                v = ((const float4*)A)[(size_t)gr * 32 + c4];
            }
        }
        uint2 hv, lv;
        split4(v, hv, lv);
        int o = row * SP_U32 + c4 * 2;
        *(uint2*)&sAh[o] = hv;
        *(uint2*)&sAl[o] = lv;
    }
    __syncthreads();

    float acc[16][4];
    #pragma unroll
    for (int t = 0; t < 16; t++) {
        acc[t][0] = 0.f; acc[t][1] = 0.f; acc[t][2] = 0.f; acc[t][3] = 0.f;
    }
    int l4 = lane >> 2, lm = lane & 3;
    int m0 = wid << 4;
    for (int p = 0; p < 3; p++) {            // hi*hi, hi*lo(B), lo(A)*hi
        const uint32_t* Ap = (p == 2) ? sAl : sAh;
        const uint32_t* Bp = (p == 1) ? sBl : sBh;
        #pragma unroll
        for (int ks = 0; ks < 8; ks++) {
            int ku = ks * 8 + lm;
            int au = (m0 + l4) * SP_U32 + ku;
            uint32_t a0 = Ap[au];
            uint32_t a1 = Ap[au + 8 * SP_U32];
            uint32_t a2 = Ap[au + 4];
            uint32_t a3 = Ap[au + 8 * SP_U32 + 4];
            #pragma unroll
            for (int nt = 0; nt < 16; nt++) {
                int bu = (nt * 8 + l4) * SP_U32 + ku;
                mma_bf16(acc[nt], a0, a1, a2, a3, Bp[bu], Bp[bu + 4]);
            }
        }
    }

    int r_lo = row0 + m0 + l4;
    int r_hi = r_lo + 8;
    #pragma unroll
    for (int nt = 0; nt < 16; nt++) {
        int col = nt * 8 + lm * 2;
        if (r_lo < M)
            *(__half2*)&C[(size_t)r_lo * 128 + col] =
                __float22half2_rn(make_float2(acc[nt][0], acc[nt][1]));
        if (r_hi < M)
            *(__half2*)&C[(size_t)r_hi * 128 + col] =
                __float22half2_rn(make_float2(acc[nt][2], acc[nt][3]));
    }
}

// ---------------------------------------------------------------------------
// Gather-based SpMM on fp16 features, fp32 accumulation, full occupancy.
// HALF_OUT: write fp16 (layer 1 -> Zh); else fp32 (final output).
template <bool HALF_OUT>
__global__ void __launch_bounds__(256) spmm_kernel(const uint2* __restrict__ Hh,
                                                   const float* __restrict__ dinv,
                                                   const int* __restrict__ rowptr,
                                                   const int2* __restrict__ epack,
                                                   const float* __restrict__ bias,
                                                   void* __restrict__ Out, int N) {
    int gw = (blockIdx.x * blockDim.x + threadIdx.x) >> 5;
    int lane = threadIdx.x & 31;
    if (gw >= N) return;
    float di = __ldg(&dinv[gw]);
    float s = di * di;
    uint2 hv = __ldg(&Hh[(size_t)gw * 32 + lane]);
    float2 h0 = __half22float2(*(__half2*)&hv.x);
    float2 h1 = __half22float2(*(__half2*)&hv.y);
    float4 acc = make_float4(s * h0.x, s * h0.y, s * h1.x, s * h1.y);
    int beg = __ldg(&rowptr[gw]), end = __ldg(&rowptr[gw + 1]);
    #pragma unroll 4
    for (int i = beg; i < end; i++) {
        int2 e = __ldg(&epack[i]);
        float w = __int_as_float(e.y);
        uint2 v = __ldg(&Hh[(size_t)e.x * 32 + lane]);
        float2 f0 = __half22float2(*(__half2*)&v.x);
        float2 f1 = __half22float2(*(__half2*)&v.y);
        acc.x += w * f0.x; acc.y += w * f0.y;
        acc.z += w * f1.x; acc.w += w * f1.y;
    }
    float4 bb = __ldg(&((const float4*)bias)[lane]);
    float4 o;
    o.x = fmaxf(acc.x + bb.x, 0.f);
    o.y = fmaxf(acc.y + bb.y, 0.f);
    o.z = fmaxf(acc.z + bb.z, 0.f);
    o.w = fmaxf(acc.w + bb.w, 0.f);
    if (HALF_OUT) {
        uint2 pk;
        *(__half2*)&pk.x = __float22half2_rn(make_float2(o.x, o.y));
        *(__half2*)&pk.y = __float22half2_rn(make_float2(o.z, o.w));
        ((uint2*)Out)[(size_t)gw * 32 + lane] = pk;
    } else {
        ((float4*)Out)[(size_t)gw * 32 + lane] = o;
    }
}

// ---------------------------------------------------------------------------
extern "C" void kernel_launch(void* const* d_in, const int* in_sizes, int n_in,
                              void* d_out, int out_size) {
    const float* x  = (const float*)d_in[0];
    const void*  ei = d_in[1];
    const float* ew = (const float*)d_in[2];
    const float* W1 = (const float*)d_in[3];
    const float* b1 = (const float*)d_in[4];
    const float* W2 = (const float*)d_in[5];
    const float* b2 = (const float*)d_in[6];
    float* out = (float*)d_out;

    int N = in_sizes[0] / DIM;
    int E = in_sizes[2];

    float* deg;
    __half *Hh, *Zh;
    int *cnt, *rowptr, *bsum, *flag;
    int2 *stage, *epack;
    unsigned short *w1h, *w1l, *w2h, *w2l;
    cudaGetSymbolAddress((void**)&deg,    g_dinv);
    cudaGetSymbolAddress((void**)&cnt,    g_cnt);
    cudaGetSymbolAddress((void**)&rowptr, g_rowptr);
    cudaGetSymbolAddress((void**)&bsum,   g_bsum);
    cudaGetSymbolAddress((void**)&flag,   g_is64);
    cudaGetSymbolAddress((void**)&stage,  g_stage);
    cudaGetSymbolAddress((void**)&epack,  g_edge);
    cudaGetSymbolAddress((void**)&Hh,     g_Hh);
    cudaGetSymbolAddress((void**)&Zh,     g_Zh);
    cudaGetSymbolAddress((void**)&w1h,    g_W1hi);
    cudaGetSymbolAddress((void**)&w1l,    g_W1lo);
    cudaGetSymbolAddress((void**)&w2h,    g_W2hi);
    cudaGetSymbolAddress((void**)&w2l,    g_W2lo);

    cudaFuncSetAttribute(tcmm_kernel<false>, cudaFuncAttributeMaxDynamicSharedMemorySize, TC_SMEM);
    cudaFuncSetAttribute(tcmm_kernel<true>,  cudaFuncAttributeMaxDynamicSharedMemorySize, TC_SMEM);

    int eb = (E + 255) / 256;
    int nb = (N + 255) / 256;
    int nblk = (N + 1023) / 1024;
    int mmb = (N + 127) / 128;
    int spb = (N * 32 + 255) / 256;

    // CSR build (single stream)
    zero_probe_kernel<<<nb, 256>>>(deg, cnt, N, (const long long*)ei, flag);
    decode_hist_kernel<<<eb, 256>>>(ei, ew, flag, deg, cnt, stage, E);
    scan_block_kernel<<<nblk, 1024>>>(cnt, rowptr, bsum, deg, N);
    scan_sums_kernel<<<1, 128>>>(bsum, nblk);
    add_off_kernel<<<nb, 256>>>(rowptr, bsum, cnt, N, E);
    place_kernel<<<eb, 256>>>(stage, ew, deg, rowptr, cnt, epack, E);

    wprep_kernel<<<128, 256>>>(W1, W2, w1h, w1l, w2h, w2l);

    // Layer 1
    tcmm_kernel<false><<<mmb, 256, TC_SMEM>>>(x, (const uint32_t*)w1h, (const uint32_t*)w1l, Hh, N);
    spmm_kernel<true><<<spb, 256>>>((const uint2*)Hh, deg, rowptr, epack, b1, Zh, N);
    // Layer 2
    tcmm_kernel<true><<<mmb, 256, TC_SMEM>>>(Zh, (const uint32_t*)w2h, (const uint32_t*)w2l, Hh, N);
    spmm_kernel<false><<<spb, 256>>>((const uint2*)Hh, deg, rowptr, epack, b2, out, N);
}